// round 14
// baseline (speedup 1.0000x reference)
#include <cuda_runtime.h>
#include <cuda_fp16.h>
#include <cstdint>

#define N_NODES 100000
#define N_EDGES 1600000
#define D 64
#define TILE_M 256
#define PAD 96                                  // adjacency slots per node
#define NODE_BLOCKS ((N_NODES + TILE_M - 1) / TILE_M)  // 391

#define A_STRIDE 136   // halves per A row (128 + 8 pad)
#define B_STRIDE 136   // halves per B row (128 + 8 pad)

// SMEM layout (bytes, dynamic)
#define SM_BIAS 0
#define SM_FC   256
#define SM_OUT  512                              // 256 floats = 1024 B
#define SM_A    2048
#define SM_BHI  (SM_A + 256 * A_STRIDE * 2)      // +69632
#define SM_BLO  (SM_BHI + 64 * B_STRIDE * 2)     // +17408
#define SMEM_TOTAL (SM_BLO + 64 * B_STRIDE * 2)  // 106496 bytes

// Scratch (allocation-free: __device__ globals; zero-initialized at load)
__device__ __half g_x16[(size_t)N_NODES * D];
__device__ __half g_h16[(size_t)N_NODES * D];
__device__ __half g_whi[2][64 * 128];   // pre-transposed hi weights [n][k]
__device__ __half g_wlo[2][64 * 128];   // pre-transposed lo weights [n][k]
__device__ int   g_count[N_NODES];      // zero on entry; layer-2 kernel clears
__device__ int   g_nbr[(size_t)N_NODES * PAD];

// ---------------------------------------------------------------------------
// helpers
// ---------------------------------------------------------------------------
__device__ __forceinline__ void mma_f16(float* d, const uint32_t* a,
                                        uint32_t b0, uint32_t b1) {
    asm volatile(
        "mma.sync.aligned.m16n8k16.row.col.f32.f16.f16.f32 "
        "{%0,%1,%2,%3}, {%4,%5,%6,%7}, {%8,%9}, {%0,%1,%2,%3};"
        : "+f"(d[0]), "+f"(d[1]), "+f"(d[2]), "+f"(d[3])
        : "r"(a[0]), "r"(a[1]), "r"(a[2]), "r"(a[3]), "r"(b0), "r"(b1));
}

__device__ __forceinline__ void h_split(float v, __half& h, __half& l) {
    h = __float2half_rn(v);
    l = __float2half_rn(v - __half2float(h));
}
__device__ __forceinline__ uint32_t h2u(__half2 h) {
    return *reinterpret_cast<uint32_t*>(&h);
}

// ---------------------------------------------------------------------------
// One-pass build (R11 form, overlapping ranges — measured fastest):
//   i < N_EDGES/2      : 2 edges -> atomic slot claim + padded write
//   i < N_NODES*D/4    : x float4 -> 4 halves
//   i < 2*8192         : weight transpose + hi/lo split
// ---------------------------------------------------------------------------
__global__ void build_kernel(const int* __restrict__ src,
                             const int* __restrict__ dst,
                             const float* __restrict__ x,
                             const float* __restrict__ Wl1,
                             const float* __restrict__ Wr1,
                             const float* __restrict__ Wl2,
                             const float* __restrict__ Wr2) {
    int i = blockIdx.x * blockDim.x + threadIdx.x;
    if (i < N_EDGES / 2) {
        int2 s = ((const int2*)src)[i];
        int2 d = ((const int2*)dst)[i];
        int p0 = atomicAdd(&g_count[d.x], 1);
        int p1 = atomicAdd(&g_count[d.y], 1);
        if (p0 < PAD) g_nbr[(size_t)d.x * PAD + p0] = s.x;
        if (p1 < PAD) g_nbr[(size_t)d.y * PAD + p1] = s.y;
    }
    if (i < N_NODES * D / 4) {
        float4 v = ((const float4*)x)[i];
        uint2 u;
        u.x = h2u(__floats2half2_rn(v.x, v.y));
        u.y = h2u(__floats2half2_rn(v.z, v.w));
        ((uint2*)g_x16)[i] = u;
    }
    if (i < 2 * 8192) {
        int L = i >> 13;
        int idx = i & 8191;
        int k = idx >> 6;
        int n = idx & 63;
        const float* Wl = L ? Wl2 : Wl1;
        const float* Wr = L ? Wr2 : Wr1;
        float w = (k < 64) ? Wl[idx] : Wr[idx - 4096];
        __half h, l;
        h_split(w, h, l);
        g_whi[L][n * 128 + k] = h;
        g_wlo[L][n * 128 + k] = l;
    }
}

// ---------------------------------------------------------------------------
// Fused tile kernel, TILE_M=256: fp16 gather -> 2-pass mma.sync f16
//   A = [mean_agg | feat]  (256 x 128 halves, fp16)
//   B = Wcat^T  (64 x 128), fp16 hi/lo, precomputed
//   Y = relu(A @ B^T + bl)
// FINAL=false: Y -> g_h16 ; FINAL=true: out = Y @ Wfc + bfc, clears g_count
// Block = 512 threads = 16 warps; warp w: m-band (w>>1)*32, n-half (w&1)*32.
// Each warp computes m32 x n32 (two m16 MMA tiles per B fragment load).
// ---------------------------------------------------------------------------
template <bool FINAL>
__global__ void __launch_bounds__(512, 2) fused_tile_kernel(
    const __half* __restrict__ Whi,
    const __half* __restrict__ Wlo,
    const float* __restrict__ bl,
    const float* __restrict__ Wfc,
    const float* __restrict__ bfc,
    float* __restrict__ outp) {
    extern __shared__ char smem[];
    float* sBias = (float*)(smem + SM_BIAS);
    float* sFc = (float*)(smem + SM_FC);
    float* sOut = (float*)(smem + SM_OUT);

    const int tid = threadIdx.x;
    const int wid = tid >> 5;
    const int lane = tid & 31;
    const int nbase = blockIdx.x * TILE_M;
    const __half* gsrc = FINAL ? g_h16 : g_x16;

    if (tid < D) {
        sBias[tid] = bl[tid];
        if (FINAL) sFc[tid] = Wfc[tid];
    }
    if (FINAL && tid < TILE_M) sOut[tid] = 0.f;

    // ---- Stage weights: coalesced uint4 loads of precomputed hi/lo tiles ----
#pragma unroll
    for (int it = 0; it < 2; it++) {
        int idx = tid + 512 * it;          // 0..1023
        int n = idx >> 4;
        int q = idx & 15;
        uint4 vh = ((const uint4*)Whi)[idx];
        uint4 vl = ((const uint4*)Wlo)[idx];
        *(uint4*)(smem + SM_BHI + ((size_t)n * B_STRIDE + q * 8) * 2) = vh;
        *(uint4*)(smem + SM_BLO + ((size_t)n * B_STRIDE + q * 8) * 2) = vl;
    }

    // ---- Stage X half (cols 64..127 of A), raw fp16 copy ----
#pragma unroll
    for (int r = 0; r < 16; r++) {
        int m = wid + 16 * r;
        int n = nbase + m;
        uint32_t pv = 0;
        if (n < N_NODES) {
            pv = ((const uint32_t*)(gsrc + (size_t)n * D))[lane];
        }
        *(uint32_t*)(smem + SM_A + ((size_t)m * A_STRIDE + 64 + lane * 2) * 2) = pv;
    }

    // ---- Gather (cols 0..63 of A): half-warp per row, no reductions ----
    // 16 lanes x uint2 (4 halves) = 128B coalesced per neighbor row.
    {
        const int hw = lane >> 4;    // half-warp 0/1
        const int c = lane & 15;     // column quad (4 halves = 8B)
#pragma unroll
        for (int i = 0; i < 8; i++) {
            const int m = (wid * 2 + hw) + 32 * i;
            const int n = nbase + m;
            float a0 = 0.f, a1 = 0.f, a2 = 0.f, a3 = 0.f;
            float b0 = 0.f, b1 = 0.f, b2 = 0.f, b3 = 0.f;
            float inv = 0.f;
            if (n < N_NODES) {
                const int cnt = g_count[n];
                const int* nb = g_nbr + (size_t)n * PAD;
                inv = cnt > 0 ? 1.0f / (float)cnt : 0.f;
                int j = 0;
                for (; j + 1 < cnt; j += 2) {
                    const int s0 = nb[j];
                    const int s1 = nb[j + 1];
                    uint2 u0 = ((const uint2*)(gsrc + (size_t)s0 * D))[c];
                    uint2 u1 = ((const uint2*)(gsrc + (size_t)s1 * D))[c];
                    float2 f0 = __half22float2(*(const __half2*)&u0.x);
                    float2 f1 = __half22float2(*(const __half2*)&u0.y);
                    float2 f2 = __half22float2(*(const __half2*)&u1.x);
                    float2 f3 = __half22float2(*(const __half2*)&u1.y);
                    a0 += f0.x; a1 += f0.y; a2 += f1.x; a3 += f1.y;
                    b0 += f2.x; b1 += f2.y; b2 += f3.x; b3 += f3.y;
                }
                if (j < cnt) {
                    const int s0 = nb[j];
                    uint2 u0 = ((const uint2*)(gsrc + (size_t)s0 * D))[c];
                    float2 f0 = __half22float2(*(const __half2*)&u0.x);
                    float2 f1 = __half22float2(*(const __half2*)&u0.y);
                    a0 += f0.x; a1 += f0.y; a2 += f1.x; a3 += f1.y;
                }
            }
            a0 += b0; a1 += b1; a2 += b2; a3 += b3;
            uint2 pk;
            pk.x = h2u(__floats2half2_rn(a0 * inv, a1 * inv));
            pk.y = h2u(__floats2half2_rn(a2 * inv, a3 * inv));
            *(uint2*)(smem + SM_A + ((size_t)m * A_STRIDE + 4 * c) * 2) = pk;
        }
    }

    __syncthreads();

    // Layer 2 consumed g_count — clear it for the next harness call.
    if (FINAL && tid < TILE_M) {
        int n = nbase + tid;
        if (n < N_NODES) g_count[n] = 0;
    }

    // ---- Dense: warp computes m32 x n32; B fragments amortized over 32 rows ----
    const int g = lane >> 2;
    const int t = lane & 3;
    const int mb = wid >> 1;      // m-band 0..7 (32 rows each)
    const int nh = wid & 1;       // n-half 0..1

    float acc[2][4][4];
#pragma unroll
    for (int ti = 0; ti < 2; ti++)
#pragma unroll
        for (int s = 0; s < 4; s++)
#pragma unroll
            for (int q = 0; q < 4; q++) acc[ti][s][q] = 0.f;

    const char* pA = smem + SM_A;
    const char* pBhi = smem + SM_BHI;
    const char* pBlo = smem + SM_BLO;
    const size_t rowT0 = (size_t)(mb * 32 + g) * A_STRIDE;       // m-tile 0
    const size_t rowT1 = rowT0 + (size_t)16 * A_STRIDE;          // m-tile 1

#pragma unroll
    for (int ks = 0; ks < 8; ks++) {
        const int k0 = ks * 16;
        uint32_t a[2][4];
        a[0][0] = *(const uint32_t*)(pA + (rowT0 + k0 + 2 * t) * 2);
        a[0][1] = *(const uint32_t*)(pA + (rowT0 + 8 * A_STRIDE + k0 + 2 * t) * 2);
        a[0][2] = *(const uint32_t*)(pA + (rowT0 + k0 + 8 + 2 * t) * 2);
        a[0][3] = *(const uint32_t*)(pA + (rowT0 + 8 * A_STRIDE + k0 + 8 + 2 * t) * 2);
        a[1][0] = *(const uint32_t*)(pA + (rowT1 + k0 + 2 * t) * 2);
        a[1][1] = *(const uint32_t*)(pA + (rowT1 + 8 * A_STRIDE + k0 + 2 * t) * 2);
        a[1][2] = *(const uint32_t*)(pA + (rowT1 + k0 + 8 + 2 * t) * 2);
        a[1][3] = *(const uint32_t*)(pA + (rowT1 + 8 * A_STRIDE + k0 + 8 + 2 * t) * 2);
#pragma unroll
        for (int sub = 0; sub < 4; sub++) {
            const int n = nh * 32 + sub * 8 + g;
            const size_t rowB = (size_t)n * B_STRIDE;
            uint32_t bh0 = *(const uint32_t*)(pBhi + (rowB + k0 + 2 * t) * 2);
            uint32_t bh1 = *(const uint32_t*)(pBhi + (rowB + k0 + 8 + 2 * t) * 2);
            uint32_t bl0 = *(const uint32_t*)(pBlo + (rowB + k0 + 2 * t) * 2);
            uint32_t bl1 = *(const uint32_t*)(pBlo + (rowB + k0 + 8 + 2 * t) * 2);
            mma_f16(acc[0][sub], a[0], bh0, bh1);
            mma_f16(acc[0][sub], a[0], bl0, bl1);
            mma_f16(acc[1][sub], a[1], bh0, bh1);
            mma_f16(acc[1][sub], a[1], bl0, bl1);
        }
    }

    // ---- Epilogue ----
    if (!FINAL) {
#pragma unroll
        for (int ti = 0; ti < 2; ti++) {
            const int m0 = mb * 32 + 16 * ti + g;
            const int m1 = m0 + 8;
#pragma unroll
            for (int sub = 0; sub < 4; sub++) {
                const int col = nh * 32 + sub * 8 + 2 * t;
                const float b0 = sBias[col];
                const float b1 = sBias[col + 1];
                const int n0 = nbase + m0;
                const int n1 = nbase + m1;
                if (n0 < N_NODES) {
                    float v0 = fmaxf(acc[ti][sub][0] + b0, 0.f);
                    float v1 = fmaxf(acc[ti][sub][1] + b1, 0.f);
                    *(uint32_t*)((char*)g_h16 + ((size_t)n0 * D + col) * 2) =
                        h2u(__floats2half2_rn(v0, v1));
                }
                if (n1 < N_NODES) {
                    float v0 = fmaxf(acc[ti][sub][2] + b0, 0.f);
                    float v1 = fmaxf(acc[ti][sub][3] + b1, 0.f);
                    *(uint32_t*)((char*)g_h16 + ((size_t)n1 * D + col) * 2) =
                        h2u(__floats2half2_rn(v0, v1));
                }
            }
        }
    } else {
#pragma unroll
        for (int ti = 0; ti < 2; ti++) {
            float p0 = 0.f, p1 = 0.f;
#pragma unroll
            for (int sub = 0; sub < 4; sub++) {
                const int col = nh * 32 + sub * 8 + 2 * t;
                const float b0 = sBias[col];
                const float b1 = sBias[col + 1];
                const float f0 = sFc[col];
                const float f1 = sFc[col + 1];
                p0 += fmaxf(acc[ti][sub][0] + b0, 0.f) * f0 +
                      fmaxf(acc[ti][sub][1] + b1, 0.f) * f1;
                p1 += fmaxf(acc[ti][sub][2] + b0, 0.f) * f0 +
                      fmaxf(acc[ti][sub][3] + b1, 0.f) * f1;
            }
            p0 += __shfl_xor_sync(0xFFFFFFFFu, p0, 1);
            p0 += __shfl_xor_sync(0xFFFFFFFFu, p0, 2);
            p1 += __shfl_xor_sync(0xFFFFFFFFu, p1, 1);
            p1 += __shfl_xor_sync(0xFFFFFFFFu, p1, 2);
            if (t == 0) {
                const int m0 = mb * 32 + 16 * ti + g;
                atomicAdd(sOut + m0, p0);
                atomicAdd(sOut + m0 + 8, p1);
            }
        }
        __syncthreads();
        if (tid < TILE_M) {
            int n = nbase + tid;
            if (n < N_NODES) outp[n] = sOut[tid] + bfc[0];
        }
    }
}

// ---------------------------------------------------------------------------
// Launch
// ---------------------------------------------------------------------------
extern "C" void kernel_launch(void* const* d_in, const int* in_sizes, int n_in,
                              void* d_out, int out_size) {
    const float* x = (const float*)d_in[0];
    const int* ei = (const int*)d_in[1];
    const float* Wl1 = (const float*)d_in[2];
    const float* bl1 = (const float*)d_in[3];
    const float* Wr1 = (const float*)d_in[4];
    const float* Wl2 = (const float*)d_in[5];
    const float* bl2 = (const float*)d_in[6];
    const float* Wr2 = (const float*)d_in[7];
    const float* Wfc = (const float*)d_in[8];
    const float* bfc = (const float*)d_in[9];
    float* out = (float*)d_out;

    const int* src = ei;
    const int* dst = ei + N_EDGES;

    const int bblk = (N_NODES * D / 4 + 255) / 256;   // 6250: covers all tasks

    cudaFuncSetAttribute(fused_tile_kernel<false>,
                         cudaFuncAttributeMaxDynamicSharedMemorySize, SMEM_TOTAL);
    cudaFuncSetAttribute(fused_tile_kernel<true>,
                         cudaFuncAttributeMaxDynamicSharedMemorySize, SMEM_TOTAL);

    __half* whi_dev = nullptr;
    __half* wlo_dev = nullptr;
    cudaGetSymbolAddress((void**)&whi_dev, g_whi);
    cudaGetSymbolAddress((void**)&wlo_dev, g_wlo);

    // One-pass build (g_count is zero on entry; layer-2 kernel re-zeroes)
    build_kernel<<<bblk, 256>>>(src, dst, x, Wl1, Wr1, Wl2, Wr2);

    // Layer 1 (fused fp16 gather + 2-pass mma.sync dense)
    fused_tile_kernel<false><<<NODE_BLOCKS, 512, SMEM_TOTAL>>>(
        whi_dev, wlo_dev, bl1, nullptr, nullptr, nullptr);

    // Layer 2 + head
    fused_tile_kernel<true><<<NODE_BLOCKS, 512, SMEM_TOTAL>>>(
        whi_dev + 64 * 128, wlo_dev + 64 * 128, bl2, Wfc, bfc, out);
}

// round 15
// speedup vs baseline: 1.1710x; 1.1710x over previous
#include <cuda_runtime.h>
#include <cuda_fp16.h>
#include <cstdint>

#define N_NODES 100000
#define N_EDGES 1600000
#define D 64
#define TILE_M 128
#define PAD 96                                  // adjacency slots per node
#define NODE_BLOCKS ((N_NODES + TILE_M - 1) / TILE_M)  // 782

#define A_STRIDE 136   // halves per A row (128 + 8 pad)
#define B_STRIDE 136   // halves per B row (128 + 8 pad)

// SMEM layout (bytes, dynamic)
#define SM_BIAS 0
#define SM_FC   256
#define SM_OUT  512
#define SM_A    1024
#define SM_B    (SM_A + 128 * A_STRIDE * 2)     // +34816
#define SMEM_TOTAL (SM_B + 64 * B_STRIDE * 2)   // 53248 bytes

// Scratch (allocation-free: __device__ globals; zero-initialized at load)
__device__ __half g_x16[(size_t)N_NODES * D];
__device__ __half g_h16[(size_t)N_NODES * D];
__device__ __half g_w16[2][64 * 128];   // pre-transposed fp16 weights [n][k]
__device__ int   g_count[N_NODES];      // zero on entry; layer-2 kernel clears
__device__ int   g_nbr[(size_t)N_NODES * PAD];

// ---------------------------------------------------------------------------
// helpers
// ---------------------------------------------------------------------------
__device__ __forceinline__ void mma_f16(float* d, const uint32_t* a,
                                        uint32_t b0, uint32_t b1) {
    asm volatile(
        "mma.sync.aligned.m16n8k16.row.col.f32.f16.f16.f32 "
        "{%0,%1,%2,%3}, {%4,%5,%6,%7}, {%8,%9}, {%0,%1,%2,%3};"
        : "+f"(d[0]), "+f"(d[1]), "+f"(d[2]), "+f"(d[3])
        : "r"(a[0]), "r"(a[1]), "r"(a[2]), "r"(a[3]), "r"(b0), "r"(b1));
}

__device__ __forceinline__ uint32_t h2u(__half2 h) {
    return *reinterpret_cast<uint32_t*>(&h);
}

// ---------------------------------------------------------------------------
// One-pass build (R11 form, overlapping ranges — measured fastest):
//   i < N_EDGES/2      : 2 edges -> atomic slot claim + padded write
//   i < N_NODES*D/4    : x float4 -> 4 halves
//   i < 2*8192         : weight transpose + fp16 round
// ---------------------------------------------------------------------------
__global__ void build_kernel(const int* __restrict__ src,
                             const int* __restrict__ dst,
                             const float* __restrict__ x,
                             const float* __restrict__ Wl1,
                             const float* __restrict__ Wr1,
                             const float* __restrict__ Wl2,
                             const float* __restrict__ Wr2) {
    int i = blockIdx.x * blockDim.x + threadIdx.x;
    if (i < N_EDGES / 2) {
        int2 s = ((const int2*)src)[i];
        int2 d = ((const int2*)dst)[i];
        int p0 = atomicAdd(&g_count[d.x], 1);
        int p1 = atomicAdd(&g_count[d.y], 1);
        if (p0 < PAD) g_nbr[(size_t)d.x * PAD + p0] = s.x;
        if (p1 < PAD) g_nbr[(size_t)d.y * PAD + p1] = s.y;
    }
    if (i < N_NODES * D / 4) {
        float4 v = ((const float4*)x)[i];
        uint2 u;
        u.x = h2u(__floats2half2_rn(v.x, v.y));
        u.y = h2u(__floats2half2_rn(v.z, v.w));
        ((uint2*)g_x16)[i] = u;
    }
    if (i < 2 * 8192) {
        int L = i >> 13;
        int idx = i & 8191;
        int k = idx >> 6;
        int n = idx & 63;
        const float* Wl = L ? Wl2 : Wl1;
        const float* Wr = L ? Wr2 : Wr1;
        float w = (k < 64) ? Wl[idx] : Wr[idx - 4096];
        g_w16[L][n * 128 + k] = __float2half_rn(w);
    }
}

// ---------------------------------------------------------------------------
// Fused tile kernel: fp16 gather (padded adjacency) -> single-pass mma.sync
//   A = [mean_agg | feat]  (128 x 128 halves, fp16)
//   B = Wcat^T  (64 x 128), fp16, precomputed
//   Y = relu(A @ B^T + bl)
// FINAL=false: Y -> g_h16 ; FINAL=true: out = Y @ Wfc + bfc, clears g_count
// Block = 512 threads = 16 warps; warp w: m-band (w>>1)*16, n-half (w&1)*32.
// ---------------------------------------------------------------------------
template <bool FINAL>
__global__ void __launch_bounds__(512, 2) fused_tile_kernel(
    const __half* __restrict__ W16,
    const float* __restrict__ bl,
    const float* __restrict__ Wfc,
    const float* __restrict__ bfc,
    float* __restrict__ outp) {
    extern __shared__ char smem[];
    float* sBias = (float*)(smem + SM_BIAS);
    float* sFc = (float*)(smem + SM_FC);
    float* sOut = (float*)(smem + SM_OUT);

    const int tid = threadIdx.x;
    const int wid = tid >> 5;
    const int lane = tid & 31;
    const int nbase = blockIdx.x * TILE_M;
    const __half* gsrc = FINAL ? g_h16 : g_x16;

    if (tid < D) {
        sBias[tid] = bl[tid];
        if (FINAL) sFc[tid] = Wfc[tid];
    }
    if (FINAL && tid < TILE_M) sOut[tid] = 0.f;

    // ---- Stage weights: coalesced uint4 loads of precomputed fp16 tile ----
#pragma unroll
    for (int it = 0; it < 2; it++) {
        int idx = tid + 512 * it;          // 0..1023
        int n = idx >> 4;
        int q = idx & 15;
        uint4 vh = ((const uint4*)W16)[idx];
        *(uint4*)(smem + SM_B + ((size_t)n * B_STRIDE + q * 8) * 2) = vh;
    }

    // ---- Stage X half (cols 64..127 of A), raw fp16 copy ----
#pragma unroll
    for (int r = 0; r < 8; r++) {
        int m = wid + 16 * r;
        int n = nbase + m;
        uint32_t pv = 0;
        if (n < N_NODES) {
            pv = ((const uint32_t*)(gsrc + (size_t)n * D))[lane];
        }
        *(uint32_t*)(smem + SM_A + ((size_t)m * A_STRIDE + 64 + lane * 2) * 2) = pv;
    }

    // ---- Gather (cols 0..63 of A): half-warp per row, no reductions ----
    // 16 lanes x uint2 (4 halves) = 128B coalesced per neighbor row.
    {
        const int hw = lane >> 4;    // half-warp 0/1
        const int c = lane & 15;     // column quad (4 halves = 8B)
#pragma unroll
        for (int i = 0; i < 4; i++) {
            const int m = (wid * 2 + hw) + 32 * i;
            const int n = nbase + m;
            float a0 = 0.f, a1 = 0.f, a2 = 0.f, a3 = 0.f;
            float b0 = 0.f, b1 = 0.f, b2 = 0.f, b3 = 0.f;
            float inv = 0.f;
            if (n < N_NODES) {
                const int cnt = g_count[n];
                const int* nb = g_nbr + (size_t)n * PAD;
                inv = cnt > 0 ? 1.0f / (float)cnt : 0.f;
                int j = 0;
                for (; j + 1 < cnt; j += 2) {
                    const int s0 = nb[j];
                    const int s1 = nb[j + 1];
                    uint2 u0 = ((const uint2*)(gsrc + (size_t)s0 * D))[c];
                    uint2 u1 = ((const uint2*)(gsrc + (size_t)s1 * D))[c];
                    float2 f0 = __half22float2(*(const __half2*)&u0.x);
                    float2 f1 = __half22float2(*(const __half2*)&u0.y);
                    float2 f2 = __half22float2(*(const __half2*)&u1.x);
                    float2 f3 = __half22float2(*(const __half2*)&u1.y);
                    a0 += f0.x; a1 += f0.y; a2 += f1.x; a3 += f1.y;
                    b0 += f2.x; b1 += f2.y; b2 += f3.x; b3 += f3.y;
                }
                if (j < cnt) {
                    const int s0 = nb[j];
                    uint2 u0 = ((const uint2*)(gsrc + (size_t)s0 * D))[c];
                    float2 f0 = __half22float2(*(const __half2*)&u0.x);
                    float2 f1 = __half22float2(*(const __half2*)&u0.y);
                    a0 += f0.x; a1 += f0.y; a2 += f1.x; a3 += f1.y;
                }
            }
            a0 += b0; a1 += b1; a2 += b2; a3 += b3;
            uint2 pk;
            pk.x = h2u(__floats2half2_rn(a0 * inv, a1 * inv));
            pk.y = h2u(__floats2half2_rn(a2 * inv, a3 * inv));
            *(uint2*)(smem + SM_A + ((size_t)m * A_STRIDE + 4 * c) * 2) = pk;
        }
    }

    __syncthreads();

    // Layer 2 consumed g_count — clear it for the next harness call.
    if (FINAL && tid < TILE_M) {
        int n = nbase + tid;
        if (n < N_NODES) g_count[n] = 0;
    }

    // ---- Dense: Y = A @ B^T via mma.sync f16, single pass ----
    const int g = lane >> 2;
    const int t = lane & 3;
    const int mb = wid >> 1;      // m-band 0..7
    const int nh = wid & 1;       // n-half 0..1

    float acc[4][4];
#pragma unroll
    for (int s = 0; s < 4; s++)
#pragma unroll
        for (int q = 0; q < 4; q++) acc[s][q] = 0.f;

    const char* pA = smem + SM_A;
    const char* pB = smem + SM_B;
    const size_t rowA = (size_t)(mb * 16 + g) * A_STRIDE;
    const size_t rowA8 = rowA + (size_t)8 * A_STRIDE;

#pragma unroll
    for (int ks = 0; ks < 8; ks++) {
        const int k0 = ks * 16;
        uint32_t a[4];
        a[0] = *(const uint32_t*)(pA + (rowA + k0 + 2 * t) * 2);
        a[1] = *(const uint32_t*)(pA + (rowA8 + k0 + 2 * t) * 2);
        a[2] = *(const uint32_t*)(pA + (rowA + k0 + 8 + 2 * t) * 2);
        a[3] = *(const uint32_t*)(pA + (rowA8 + k0 + 8 + 2 * t) * 2);
#pragma unroll
        for (int sub = 0; sub < 4; sub++) {
            const int n = nh * 32 + sub * 8 + g;
            const size_t rowB = (size_t)n * B_STRIDE;
            uint32_t bh0 = *(const uint32_t*)(pB + (rowB + k0 + 2 * t) * 2);
            uint32_t bh1 = *(const uint32_t*)(pB + (rowB + k0 + 8 + 2 * t) * 2);
            mma_f16(acc[sub], a, bh0, bh1);
        }
    }

    // ---- Epilogue ----
    const int m0 = mb * 16 + g;
    const int m1 = m0 + 8;
    if (!FINAL) {
#pragma unroll
        for (int sub = 0; sub < 4; sub++) {
            const int col = nh * 32 + sub * 8 + 2 * t;
            const float b0 = sBias[col];
            const float b1 = sBias[col + 1];
            const int n0 = nbase + m0;
            const int n1 = nbase + m1;
            if (n0 < N_NODES) {
                float v0 = fmaxf(acc[sub][0] + b0, 0.f);
                float v1 = fmaxf(acc[sub][1] + b1, 0.f);
                *(uint32_t*)((char*)g_h16 + ((size_t)n0 * D + col) * 2) =
                    h2u(__floats2half2_rn(v0, v1));
            }
            if (n1 < N_NODES) {
                float v0 = fmaxf(acc[sub][2] + b0, 0.f);
                float v1 = fmaxf(acc[sub][3] + b1, 0.f);
                *(uint32_t*)((char*)g_h16 + ((size_t)n1 * D + col) * 2) =
                    h2u(__floats2half2_rn(v0, v1));
            }
        }
    } else {
        float p0 = 0.f, p1 = 0.f;
#pragma unroll
        for (int sub = 0; sub < 4; sub++) {
            const int col = nh * 32 + sub * 8 + 2 * t;
            const float b0 = sBias[col];
            const float b1 = sBias[col + 1];
            const float f0 = sFc[col];
            const float f1 = sFc[col + 1];
            p0 += fmaxf(acc[sub][0] + b0, 0.f) * f0 + fmaxf(acc[sub][1] + b1, 0.f) * f1;
            p1 += fmaxf(acc[sub][2] + b0, 0.f) * f0 + fmaxf(acc[sub][3] + b1, 0.f) * f1;
        }
        p0 += __shfl_xor_sync(0xFFFFFFFFu, p0, 1);
        p0 += __shfl_xor_sync(0xFFFFFFFFu, p0, 2);
        p1 += __shfl_xor_sync(0xFFFFFFFFu, p1, 1);
        p1 += __shfl_xor_sync(0xFFFFFFFFu, p1, 2);
        if (t == 0) {
            atomicAdd(sOut + m0, p0);
            atomicAdd(sOut + m1, p1);
        }
        __syncthreads();
        if (tid < TILE_M) {
            int n = nbase + tid;
            if (n < N_NODES) outp[n] = sOut[tid] + bfc[0];
        }
    }
}

// ---------------------------------------------------------------------------
// Launch
// ---------------------------------------------------------------------------
extern "C" void kernel_launch(void* const* d_in, const int* in_sizes, int n_in,
                              void* d_out, int out_size) {
    const float* x = (const float*)d_in[0];
    const int* ei = (const int*)d_in[1];
    const float* Wl1 = (const float*)d_in[2];
    const float* bl1 = (const float*)d_in[3];
    const float* Wr1 = (const float*)d_in[4];
    const float* Wl2 = (const float*)d_in[5];
    const float* bl2 = (const float*)d_in[6];
    const float* Wr2 = (const float*)d_in[7];
    const float* Wfc = (const float*)d_in[8];
    const float* bfc = (const float*)d_in[9];
    float* out = (float*)d_out;

    const int* src = ei;
    const int* dst = ei + N_EDGES;

    const int bblk = (N_NODES * D / 4 + 255) / 256;   // 6250: covers all tasks

    cudaFuncSetAttribute(fused_tile_kernel<false>,
                         cudaFuncAttributeMaxDynamicSharedMemorySize, SMEM_TOTAL);
    cudaFuncSetAttribute(fused_tile_kernel<true>,
                         cudaFuncAttributeMaxDynamicSharedMemorySize, SMEM_TOTAL);

    __half* w_dev = nullptr;
    cudaGetSymbolAddress((void**)&w_dev, g_w16);

    // One-pass build (g_count is zero on entry; layer-2 kernel re-zeroes)
    build_kernel<<<bblk, 256>>>(src, dst, x, Wl1, Wr1, Wl2, Wr2);

    // Layer 1 (fused fp16 gather + single-pass mma.sync dense)
    fused_tile_kernel<false><<<NODE_BLOCKS, 512, SMEM_TOTAL>>>(
        w_dev, bl1, nullptr, nullptr, nullptr);

    // Layer 2 + head
    fused_tile_kernel<true><<<NODE_BLOCKS, 512, SMEM_TOTAL>>>(
        w_dev + 64 * 128, bl2, Wfc, bfc, out);
}

// round 16
// speedup vs baseline: 1.2368x; 1.0562x over previous
#include <cuda_runtime.h>
#include <cuda_fp16.h>
#include <cstdint>

#define N_NODES 100000
#define N_EDGES 1600000
#define D 64
#define TILE_M 128
#define PAD 96                                  // adjacency slots per node
#define NODE_BLOCKS ((N_NODES + TILE_M - 1) / TILE_M)  // 782

#define A_STRIDE 136   // halves per A row (128 + 8 pad)
#define B_STRIDE 136   // halves per B row (128 + 8 pad)

// SMEM layout (bytes, dynamic)
#define SM_BIAS 0
#define SM_FC   256
#define SM_OUT  512
#define SM_A    1024
#define SM_B    (SM_A + 128 * A_STRIDE * 2)     // +34816
#define SMEM_TOTAL (SM_B + 64 * B_STRIDE * 2)   // 53248 bytes -> 3 blocks/SM

// Scratch (allocation-free: __device__ globals; zero-initialized at load)
__device__ __half g_x16[(size_t)N_NODES * D];
__device__ __half g_h16[(size_t)N_NODES * D];
__device__ __half g_w16[2][64 * 128];   // pre-transposed fp16 weights [n][k]
__device__ int   g_count[N_NODES];      // zero on entry; layer-2 kernel clears
__device__ int   g_nbr[(size_t)N_NODES * PAD];

// ---------------------------------------------------------------------------
// helpers
// ---------------------------------------------------------------------------
__device__ __forceinline__ void mma_f16(float* d, const uint32_t* a,
                                        uint32_t b0, uint32_t b1) {
    asm volatile(
        "mma.sync.aligned.m16n8k16.row.col.f32.f16.f16.f32 "
        "{%0,%1,%2,%3}, {%4,%5,%6,%7}, {%8,%9}, {%0,%1,%2,%3};"
        : "+f"(d[0]), "+f"(d[1]), "+f"(d[2]), "+f"(d[3])
        : "r"(a[0]), "r"(a[1]), "r"(a[2]), "r"(a[3]), "r"(b0), "r"(b1));
}

__device__ __forceinline__ uint32_t h2u(__half2 h) {
    return *reinterpret_cast<uint32_t*>(&h);
}

// ---------------------------------------------------------------------------
// One-pass build (overlapping ranges — measured fastest):
//   i < N_EDGES/2      : 2 edges -> atomic slot claim + padded write
//   i < N_NODES*D/4    : x float4 -> 4 halves
//   i < 2*8192         : weight transpose + fp16 round
// ---------------------------------------------------------------------------
__global__ void build_kernel(const int* __restrict__ src,
                             const int* __restrict__ dst,
                             const float* __restrict__ x,
                             const float* __restrict__ Wl1,
                             const float* __restrict__ Wr1,
                             const float* __restrict__ Wl2,
                             const float* __restrict__ Wr2) {
    int i = blockIdx.x * blockDim.x + threadIdx.x;
    if (i < N_EDGES / 2) {
        int2 s = ((const int2*)src)[i];
        int2 d = ((const int2*)dst)[i];
        int p0 = atomicAdd(&g_count[d.x], 1);
        int p1 = atomicAdd(&g_count[d.y], 1);
        if (p0 < PAD) g_nbr[(size_t)d.x * PAD + p0] = s.x;
        if (p1 < PAD) g_nbr[(size_t)d.y * PAD + p1] = s.y;
    }
    if (i < N_NODES * D / 4) {
        float4 v = ((const float4*)x)[i];
        uint2 u;
        u.x = h2u(__floats2half2_rn(v.x, v.y));
        u.y = h2u(__floats2half2_rn(v.z, v.w));
        ((uint2*)g_x16)[i] = u;
    }
    if (i < 2 * 8192) {
        int L = i >> 13;
        int idx = i & 8191;
        int k = idx >> 6;
        int n = idx & 63;
        const float* Wl = L ? Wl2 : Wl1;
        const float* Wr = L ? Wr2 : Wr1;
        float w = (k < 64) ? Wl[idx] : Wr[idx - 4096];
        g_w16[L][n * 128 + k] = __float2half_rn(w);
    }
}

// ---------------------------------------------------------------------------
// Fused tile kernel: fp16 gather (padded adjacency) -> single-pass mma.sync
//   A = [mean_agg | feat]  (128 x 128 halves, fp16)
//   B = Wcat^T  (64 x 128), fp16, precomputed
//   Y = relu(A @ B^T + bl)
// FINAL=false: Y -> g_h16 ; FINAL=true: out = Y @ Wfc + bfc, clears g_count
// Block = 512 threads = 16 warps; warp w: m-band (w>>1)*16, n-half (w&1)*32.
// 3 blocks/SM: one block's gather overlaps another's MMA/epilogue.
// ---------------------------------------------------------------------------
template <bool FINAL>
__global__ void __launch_bounds__(512, 3) fused_tile_kernel(
    const __half* __restrict__ W16,
    const float* __restrict__ bl,
    const float* __restrict__ Wfc,
    const float* __restrict__ bfc,
    float* __restrict__ outp) {
    extern __shared__ char smem[];
    float* sBias = (float*)(smem + SM_BIAS);
    float* sFc = (float*)(smem + SM_FC);
    float* sOut = (float*)(smem + SM_OUT);

    const int tid = threadIdx.x;
    const int wid = tid >> 5;
    const int lane = tid & 31;
    const int nbase = blockIdx.x * TILE_M;
    const __half* gsrc = FINAL ? g_h16 : g_x16;

    if (tid < D) {
        sBias[tid] = bl[tid];
        if (FINAL) sFc[tid] = Wfc[tid];
    }
    if (FINAL && tid < TILE_M) sOut[tid] = 0.f;

    // ---- Stage weights: coalesced uint4 loads of precomputed fp16 tile ----
#pragma unroll
    for (int it = 0; it < 2; it++) {
        int idx = tid + 512 * it;          // 0..1023
        int n = idx >> 4;
        int q = idx & 15;
        uint4 vh = ((const uint4*)W16)[idx];
        *(uint4*)(smem + SM_B + ((size_t)n * B_STRIDE + q * 8) * 2) = vh;
    }

    // ---- Stage X half (cols 64..127 of A), raw fp16 copy ----
#pragma unroll
    for (int r = 0; r < 8; r++) {
        int m = wid + 16 * r;
        int n = nbase + m;
        uint32_t pv = 0;
        if (n < N_NODES) {
            pv = ((const uint32_t*)(gsrc + (size_t)n * D))[lane];
        }
        *(uint32_t*)(smem + SM_A + ((size_t)m * A_STRIDE + 64 + lane * 2) * 2) = pv;
    }

    // ---- Gather (cols 0..63 of A): half-warp per row, no reductions ----
    // 16 lanes x uint2 (4 halves) = 128B coalesced per neighbor row.
    {
        const int hw = lane >> 4;    // half-warp 0/1
        const int c = lane & 15;     // column quad (4 halves = 8B)
#pragma unroll
        for (int i = 0; i < 4; i++) {
            const int m = (wid * 2 + hw) + 32 * i;
            const int n = nbase + m;
            float a0 = 0.f, a1 = 0.f, a2 = 0.f, a3 = 0.f;
            float b0 = 0.f, b1 = 0.f, b2 = 0.f, b3 = 0.f;
            float inv = 0.f;
            if (n < N_NODES) {
                const int cnt = g_count[n];
                const int* nb = g_nbr + (size_t)n * PAD;
                inv = cnt > 0 ? 1.0f / (float)cnt : 0.f;
                int j = 0;
                for (; j + 1 < cnt; j += 2) {
                    const int s0 = nb[j];
                    const int s1 = nb[j + 1];
                    uint2 u0 = ((const uint2*)(gsrc + (size_t)s0 * D))[c];
                    uint2 u1 = ((const uint2*)(gsrc + (size_t)s1 * D))[c];
                    float2 f0 = __half22float2(*(const __half2*)&u0.x);
                    float2 f1 = __half22float2(*(const __half2*)&u0.y);
                    float2 f2 = __half22float2(*(const __half2*)&u1.x);
                    float2 f3 = __half22float2(*(const __half2*)&u1.y);
                    a0 += f0.x; a1 += f0.y; a2 += f1.x; a3 += f1.y;
                    b0 += f2.x; b1 += f2.y; b2 += f3.x; b3 += f3.y;
                }
                if (j < cnt) {
                    const int s0 = nb[j];
                    uint2 u0 = ((const uint2*)(gsrc + (size_t)s0 * D))[c];
                    float2 f0 = __half22float2(*(const __half2*)&u0.x);
                    float2 f1 = __half22float2(*(const __half2*)&u0.y);
                    a0 += f0.x; a1 += f0.y; a2 += f1.x; a3 += f1.y;
                }
            }
            a0 += b0; a1 += b1; a2 += b2; a3 += b3;
            uint2 pk;
            pk.x = h2u(__floats2half2_rn(a0 * inv, a1 * inv));
            pk.y = h2u(__floats2half2_rn(a2 * inv, a3 * inv));
            *(uint2*)(smem + SM_A + ((size_t)m * A_STRIDE + 4 * c) * 2) = pk;
        }
    }

    __syncthreads();

    // Layer 2 consumed g_count — clear it for the next harness call.
    if (FINAL && tid < TILE_M) {
        int n = nbase + tid;
        if (n < N_NODES) g_count[n] = 0;
    }

    // ---- Dense: Y = A @ B^T via mma.sync f16, single pass ----
    const int g = lane >> 2;
    const int t = lane & 3;
    const int mb = wid >> 1;      // m-band 0..7
    const int nh = wid & 1;       // n-half 0..1

    float acc[4][4];
#pragma unroll
    for (int s = 0; s < 4; s++)
#pragma unroll
        for (int q = 0; q < 4; q++) acc[s][q] = 0.f;

    const char* pA = smem + SM_A;
    const char* pB = smem + SM_B;
    const size_t rowA = (size_t)(mb * 16 + g) * A_STRIDE;
    const size_t rowA8 = rowA + (size_t)8 * A_STRIDE;

#pragma unroll
    for (int ks = 0; ks < 8; ks++) {
        const int k0 = ks * 16;
        uint32_t a[4];
        a[0] = *(const uint32_t*)(pA + (rowA + k0 + 2 * t) * 2);
        a[1] = *(const uint32_t*)(pA + (rowA8 + k0 + 2 * t) * 2);
        a[2] = *(const uint32_t*)(pA + (rowA + k0 + 8 + 2 * t) * 2);
        a[3] = *(const uint32_t*)(pA + (rowA8 + k0 + 8 + 2 * t) * 2);
#pragma unroll
        for (int sub = 0; sub < 4; sub++) {
            const int n = nh * 32 + sub * 8 + g;
            const size_t rowB = (size_t)n * B_STRIDE;
            uint32_t bh0 = *(const uint32_t*)(pB + (rowB + k0 + 2 * t) * 2);
            uint32_t bh1 = *(const uint32_t*)(pB + (rowB + k0 + 8 + 2 * t) * 2);
            mma_f16(acc[sub], a, bh0, bh1);
        }
    }

    // ---- Epilogue ----
    const int m0 = mb * 16 + g;
    const int m1 = m0 + 8;
    if (!FINAL) {
#pragma unroll
        for (int sub = 0; sub < 4; sub++) {
            const int col = nh * 32 + sub * 8 + 2 * t;
            const float b0 = sBias[col];
            const float b1 = sBias[col + 1];
            const int n0 = nbase + m0;
            const int n1 = nbase + m1;
            if (n0 < N_NODES) {
                float v0 = fmaxf(acc[sub][0] + b0, 0.f);
                float v1 = fmaxf(acc[sub][1] + b1, 0.f);
                *(uint32_t*)((char*)g_h16 + ((size_t)n0 * D + col) * 2) =
                    h2u(__floats2half2_rn(v0, v1));
            }
            if (n1 < N_NODES) {
                float v0 = fmaxf(acc[sub][2] + b0, 0.f);
                float v1 = fmaxf(acc[sub][3] + b1, 0.f);
                *(uint32_t*)((char*)g_h16 + ((size_t)n1 * D + col) * 2) =
                    h2u(__floats2half2_rn(v0, v1));
            }
        }
    } else {
        float p0 = 0.f, p1 = 0.f;
#pragma unroll
        for (int sub = 0; sub < 4; sub++) {
            const int col = nh * 32 + sub * 8 + 2 * t;
            const float b0 = sBias[col];
            const float b1 = sBias[col + 1];
            const float f0 = sFc[col];
            const float f1 = sFc[col + 1];
            p0 += fmaxf(acc[sub][0] + b0, 0.f) * f0 + fmaxf(acc[sub][1] + b1, 0.f) * f1;
            p1 += fmaxf(acc[sub][2] + b0, 0.f) * f0 + fmaxf(acc[sub][3] + b1, 0.f) * f1;
        }
        p0 += __shfl_xor_sync(0xFFFFFFFFu, p0, 1);
        p0 += __shfl_xor_sync(0xFFFFFFFFu, p0, 2);
        p1 += __shfl_xor_sync(0xFFFFFFFFu, p1, 1);
        p1 += __shfl_xor_sync(0xFFFFFFFFu, p1, 2);
        if (t == 0) {
            atomicAdd(sOut + m0, p0);
            atomicAdd(sOut + m1, p1);
        }
        __syncthreads();
        if (tid < TILE_M) {
            int n = nbase + tid;
            if (n < N_NODES) outp[n] = sOut[tid] + bfc[0];
        }
    }
}

// ---------------------------------------------------------------------------
// Launch
// ---------------------------------------------------------------------------
extern "C" void kernel_launch(void* const* d_in, const int* in_sizes, int n_in,
                              void* d_out, int out_size) {
    const float* x = (const float*)d_in[0];
    const int* ei = (const int*)d_in[1];
    const float* Wl1 = (const float*)d_in[2];
    const float* bl1 = (const float*)d_in[3];
    const float* Wr1 = (const float*)d_in[4];
    const float* Wl2 = (const float*)d_in[5];
    const float* bl2 = (const float*)d_in[6];
    const float* Wr2 = (const float*)d_in[7];
    const float* Wfc = (const float*)d_in[8];
    const float* bfc = (const float*)d_in[9];
    float* out = (float*)d_out;

    const int* src = ei;
    const int* dst = ei + N_EDGES;

    const int bblk = (N_NODES * D / 4 + 255) / 256;   // 6250: covers all tasks

    cudaFuncSetAttribute(fused_tile_kernel<false>,
                         cudaFuncAttributeMaxDynamicSharedMemorySize, SMEM_TOTAL);
    cudaFuncSetAttribute(fused_tile_kernel<true>,
                         cudaFuncAttributeMaxDynamicSharedMemorySize, SMEM_TOTAL);

    __half* w_dev = nullptr;
    cudaGetSymbolAddress((void**)&w_dev, g_w16);

    // One-pass build (g_count is zero on entry; layer-2 kernel re-zeroes)
    build_kernel<<<bblk, 256>>>(src, dst, x, Wl1, Wr1, Wl2, Wr2);

    // Layer 1 (fused fp16 gather + single-pass mma.sync dense)
    fused_tile_kernel<false><<<NODE_BLOCKS, 512, SMEM_TOTAL>>>(
        w_dev, bl1, nullptr, nullptr, nullptr);

    // Layer 2 + head
    fused_tile_kernel<true><<<NODE_BLOCKS, 512, SMEM_TOTAL>>>(
        w_dev + 64 * 128, bl2, Wfc, bfc, out);
}